// round 7
// baseline (speedup 1.0000x reference)
#include <cuda_runtime.h>
#include <math.h>

#define H 1024
#define L 512
#define V 50257

// ---------------- scratch layout (floats) ----------------
#define OFF_ALOG   0        // attn logits (512)
#define OFF_ATT    512      // attn_applied accumulator (1024)
#define OFF_X      1536     // GRU input x (1024)
#define OFF_GI     2560     // gi (3072)
#define OFF_GH     5632     // gh (3072)
#define OFF_LOGITS 9728     // vocab logits (50257)
#define OFF_PART   59985    // 240 partial exp-sums
#define OFF_LSE    60225
#define SCRATCH_FLOATS 60240

__device__ float g_scratch[SCRATCH_FLOATS];
__device__ int   g_maxbits;   // ordered-int running max of vocab logits
__device__ int   g_count_ls;  // arrival counter: log-softmax
__device__ int   g_flag_ls;   // lse-ready flag

__device__ __forceinline__ int f2ord(float f) {
    int i = __float_as_int(f);
    return (i >= 0) ? i : (i ^ 0x7FFFFFFF);
}
__device__ __forceinline__ float ord2f(int o) {
    return __int_as_float((o >= 0) ? o : (o ^ 0x7FFFFFFF));
}

// dot of 8 front-batched float4 (1024 floats) against smem slice: MLP=8 per lane
__device__ __forceinline__ float dot8(const float4* __restrict__ wr,
                                      const float4* __restrict__ v4,
                                      int lane) {
    float4 w0 = __ldcs(wr + lane);
    float4 w1 = __ldcs(wr + lane + 32);
    float4 w2 = __ldcs(wr + lane + 64);
    float4 w3 = __ldcs(wr + lane + 96);
    float4 w4 = __ldcs(wr + lane + 128);
    float4 w5 = __ldcs(wr + lane + 160);
    float4 w6 = __ldcs(wr + lane + 192);
    float4 w7 = __ldcs(wr + lane + 224);
    float4 x0 = v4[lane],       x1 = v4[lane + 32];
    float4 x2 = v4[lane + 64],  x3 = v4[lane + 96];
    float4 x4 = v4[lane + 128], x5 = v4[lane + 160];
    float4 x6 = v4[lane + 192], x7 = v4[lane + 224];
    float a = 0.f;
    a += w0.x*x0.x + w0.y*x0.y + w0.z*x0.z + w0.w*x0.w;
    a += w1.x*x1.x + w1.y*x1.y + w1.z*x1.z + w1.w*x1.w;
    a += w2.x*x2.x + w2.y*x2.y + w2.z*x2.z + w2.w*x2.w;
    a += w3.x*x3.x + w3.y*x3.y + w3.z*x3.z + w3.w*x3.w;
    a += w4.x*x4.x + w4.y*x4.y + w4.z*x4.z + w4.w*x4.w;
    a += w5.x*x5.x + w5.y*x5.y + w5.z*x5.z + w5.w*x5.w;
    a += w6.x*x6.x + w6.y*x6.y + w6.z*x6.z + w6.w*x6.w;
    a += w7.x*x7.x + w7.y*x7.y + w7.z*x7.z + w7.w*x7.w;
    return a;
}

__device__ __forceinline__ float warp_sum(float a) {
    #pragma unroll
    for (int o = 16; o; o >>= 1) a += __shfl_xor_sync(0xFFFFFFFFu, a, o);
    return a;
}

// ---------------- N1: attn logits (blocks 0-255, 2 rows, K-split) +
//                      gh GEMV (blocks 256-1023, 4 full rows) ----------------
__global__ void __launch_bounds__(128)
k_attn_gh(const float* __restrict__ attn_W, const float* __restrict__ attn_b,
          const float* __restrict__ W_hh, const float* __restrict__ b_hh,
          const int* __restrict__ idx, const float* __restrict__ hidden,
          const float* __restrict__ emb) {
    __shared__ float sv[2 * H];
    __shared__ float spart[4];
    int t = threadIdx.x, bid = blockIdx.x;
    int warp = t >> 5, lane = t & 31;

    if (bid < 256) {
        int row_e = idx[0];
        #pragma unroll
        for (int i = t; i < 512; i += 128) {
            ((float4*)sv)[i] = (i < 256)
                ? ((const float4*)(emb + (size_t)row_e * H))[i]
                : ((const float4*)hidden)[i - 256];
        }
    } else {
        #pragma unroll
        for (int i = t; i < 256; i += 128)
            ((float4*)sv)[i] = ((const float4*)hidden)[i];
    }
    if (bid == 0) {
        #pragma unroll
        for (int i = t; i < H; i += 128) g_scratch[OFF_ATT + i] = 0.f;
        if (t == 0) { g_maxbits = 0x80000000; g_count_ls = 0; g_flag_ls = 0; }
    }
    __syncthreads();

    if (bid < 256) {
        // 2 rows/block, each row split across 2 warps (half = 1024 cols)
        int row  = bid * 2 + (warp >> 1);
        int half = warp & 1;
        const float4* wr = (const float4*)(attn_W + (size_t)row * 2 * H + half * H);
        const float4* v4 = (const float4*)(sv + half * H);
        float acc = warp_sum(dot8(wr, v4, lane));
        if (lane == 0) spart[warp] = acc;
        __syncthreads();
        if (t < 2) {
            int r = bid * 2 + t;
            g_scratch[OFF_ALOG + r] = spart[2 * t] + spart[2 * t + 1] + attn_b[r];
        }
    } else {
        int row = (bid - 256) * 4 + warp;              // 0..3071
        const float4* wr = (const float4*)(W_hh + (size_t)row * H);
        float acc = warp_sum(dot8(wr, (const float4*)sv, lane));
        if (lane == 0) g_scratch[OFF_GH + row] = acc + b_hh[row];
    }
}

// ---------------- N2: per-block softmax(512) + attn_applied partials ----------------
__global__ void __launch_bounds__(256)
k_apply(const float* __restrict__ enc, float* __restrict__ out_full) {
    __shared__ float aw[512];
    __shared__ float sred[256];
    int t = threadIdx.x;
    float v0 = g_scratch[OFF_ALOG + t];
    float v1 = g_scratch[OFF_ALOG + 256 + t];
    sred[t] = fmaxf(v0, v1);
    __syncthreads();
    #pragma unroll
    for (int s = 128; s > 0; s >>= 1) {
        if (t < s) sred[t] = fmaxf(sred[t], sred[t + s]);
        __syncthreads();
    }
    float mx = sred[0];
    __syncthreads();
    float e0 = expf(v0 - mx), e1 = expf(v1 - mx);
    sred[t] = e0 + e1;
    __syncthreads();
    #pragma unroll
    for (int s = 128; s > 0; s >>= 1) {
        if (t < s) sred[t] += sred[t + s];
        __syncthreads();
    }
    float inv = 1.f / sred[0];
    aw[t] = e0 * inv; aw[256 + t] = e1 * inv;
    __syncthreads();
    if (blockIdx.x == 0 && blockIdx.y == 0) {
        out_full[V + H + t]       = aw[t];
        out_full[V + H + 256 + t] = aw[256 + t];
    }
    int col  = blockIdx.x * 256 + t;
    int base = blockIdx.y * 32;
    float s = 0.f;
    #pragma unroll
    for (int l = 0; l < 32; l++)
        s += aw[base + l] * __ldcs(enc + (size_t)(base + l) * H + col);
    atomicAdd(&g_scratch[OFF_ATT + col], s);
}

// ---------------- N3: x = relu(cat(emb[idx], attn_applied) @ comb_W.T + b) ----------------
// 512 blocks x 128 thr: 2 rows/block, K-split across warp pairs
__global__ void __launch_bounds__(128)
k_comb(const float* __restrict__ comb_W, const float* __restrict__ comb_b,
       const int* __restrict__ idx, const float* __restrict__ emb) {
    __shared__ float sv[2 * H];
    __shared__ float spart[4];
    int t = threadIdx.x;
    int warp = t >> 5, lane = t & 31;
    int row_e = idx[0];
    #pragma unroll
    for (int i = t; i < 512; i += 128) {
        ((float4*)sv)[i] = (i < 256)
            ? ((const float4*)(emb + (size_t)row_e * H))[i]
            : ((const float4*)(g_scratch + OFF_ATT))[i - 256];
    }
    __syncthreads();
    int row  = blockIdx.x * 2 + (warp >> 1);           // 0..1023
    int half = warp & 1;
    const float4* wr = (const float4*)(comb_W + (size_t)row * 2 * H + half * H);
    const float4* v4 = (const float4*)(sv + half * H);
    float acc = warp_sum(dot8(wr, v4, lane));
    if (lane == 0) spart[warp] = acc;
    __syncthreads();
    if (t < 2) {
        int r = blockIdx.x * 2 + t;
        g_scratch[OFF_X + r] = fmaxf(spart[2 * t] + spart[2 * t + 1] + comb_b[r], 0.f);
    }
}

// ---------------- N4: gi = x @ W_ih.T + b_ih (768 blocks x 128 thr, 4 rows) ----------------
__global__ void __launch_bounds__(128)
k_gi(const float* __restrict__ W_ih, const float* __restrict__ b_ih) {
    __shared__ float sx[H];
    int t = threadIdx.x;
    #pragma unroll
    for (int i = t; i < 256; i += 128)
        ((float4*)sx)[i] = ((const float4*)(g_scratch + OFF_X))[i];
    __syncthreads();
    int warp = t >> 5, lane = t & 31;
    int row = blockIdx.x * 4 + warp;                   // 0..3071
    const float4* wr = (const float4*)(W_ih + (size_t)row * H);
    float acc = warp_sum(dot8(wr, (const float4*)sx, lane));
    if (lane == 0) g_scratch[OFF_GI + row] = acc + b_ih[row];
}

// ---------------- N5: vocab logits with GRU gates fused in prologue ----------------
// Each block recomputes h_new[1024] (deterministic: identical FP sequence per block).
// 512 threads, 16 rows/block.
__global__ void __launch_bounds__(512)
k_vocab(const float* __restrict__ out_W, const float* __restrict__ out_b,
        const float* __restrict__ hidden, float* __restrict__ out_full) {
    __shared__ float hv[H];
    __shared__ float srow[16];
    int t = threadIdx.x;
    // gates: 2 elems per thread
    #pragma unroll
    for (int k = 0; k < 2; k++) {
        int j = t + k * 512;
        float gir = __ldg(&g_scratch[OFF_GI + j]),       ghr = __ldg(&g_scratch[OFF_GH + j]);
        float giz = __ldg(&g_scratch[OFF_GI + H + j]),   ghz = __ldg(&g_scratch[OFF_GH + H + j]);
        float gin = __ldg(&g_scratch[OFF_GI + 2*H + j]), ghn = __ldg(&g_scratch[OFF_GH + 2*H + j]);
        float r = 1.f / (1.f + expf(-(gir + ghr)));
        float z = 1.f / (1.f + expf(-(giz + ghz)));
        float n = tanhf(gin + r * ghn);
        float hn = (1.f - z) * n + z * __ldg(&hidden[j]);
        hv[j] = hn;
        if (blockIdx.x == 0) out_full[V + j] = hn;     // second output
    }
    __syncthreads();
    int warp = t >> 5, lane = t & 31;
    int row = blockIdx.x * 16 + warp;
    float r = -INFINITY;
    if (row < V) {
        const float4* wr = (const float4*)(out_W + (size_t)row * H);
        float acc = warp_sum(dot8(wr, (const float4*)hv, lane));
        if (lane == 0) {
            r = acc + out_b[row];
            g_scratch[OFF_LOGITS + row] = r;
        }
    }
    if (lane == 0) srow[warp] = r;
    __syncthreads();
    if (t == 0) {
        float m = srow[0];
        #pragma unroll
        for (int w = 1; w < 16; w++) m = fmaxf(m, srow[w]);
        atomicMax(&g_maxbits, f2ord(m));
    }
}

// ---------------- N6: fused log-softmax (240 blocks, one wave, spin on lse) ----------------
#define NB_SUM 240
__global__ void __launch_bounds__(256)
k_logsoftmax(float* __restrict__ out_full) {
    __shared__ float sm[256];
    int t = threadIdx.x;
    float m = ord2f(g_maxbits);
    float s = 0.f;
    for (int i = blockIdx.x * 256 + t; i < V; i += NB_SUM * 256)
        s += expf(g_scratch[OFF_LOGITS + i] - m);
    sm[t] = s;
    __syncthreads();
    #pragma unroll
    for (int st = 128; st > 0; st >>= 1) {
        if (t < st) sm[t] += sm[t + st];
        __syncthreads();
    }
    if (t == 0) {
        g_scratch[OFF_PART + blockIdx.x] = sm[0];
        __threadfence();
        int old = atomicAdd(&g_count_ls, 1);
        if (old == NB_SUM - 1) {
            float tot = 0.f;
            #pragma unroll 8
            for (int p = 0; p < NB_SUM; p++) tot += g_scratch[OFF_PART + p];
            g_scratch[OFF_LSE] = m + logf(tot);
            __threadfence();
            atomicExch(&g_flag_ls, 1);
        }
        while (atomicAdd(&g_flag_ls, 0) == 0) { }
        __threadfence();
    }
    __syncthreads();
    float lse = g_scratch[OFF_LSE];
    for (int i = blockIdx.x * 256 + t; i < V; i += NB_SUM * 256)
        out_full[i] = g_scratch[OFF_LOGITS + i] - lse;
}

// ---------------- launch: 6 graph nodes ----------------
extern "C" void kernel_launch(void* const* d_in, const int* in_sizes, int n_in,
                              void* d_out, int out_size) {
    const int*   input_idx = (const int*)  d_in[0];
    const float* hidden    = (const float*)d_in[1];
    const float* enc       = (const float*)d_in[2];
    const float* emb       = (const float*)d_in[3];
    const float* attn_W    = (const float*)d_in[4];
    const float* attn_b    = (const float*)d_in[5];
    const float* comb_W    = (const float*)d_in[6];
    const float* comb_b    = (const float*)d_in[7];
    const float* W_ih      = (const float*)d_in[8];
    const float* b_ih      = (const float*)d_in[10];
    const float* W_hh      = (const float*)d_in[9];
    const float* b_hh      = (const float*)d_in[11];
    const float* out_W     = (const float*)d_in[12];
    const float* out_b     = (const float*)d_in[13];
    float* out = (float*)d_out;

    k_attn_gh   <<<1024, 128>>>(attn_W, attn_b, W_hh, b_hh, input_idx, hidden, emb);
    k_apply     <<<dim3(4, 16), 256>>>(enc, out);
    k_comb      <<<512, 128>>>(comb_W, comb_b, input_idx, emb);
    k_gi        <<<768, 128>>>(W_ih, b_ih);
    k_vocab     <<<(V + 15) / 16, 512>>>(out_W, out_b, hidden, out);
    k_logsoftmax<<<NB_SUM, 256>>>(out);
}

// round 8
// speedup vs baseline: 1.0307x; 1.0307x over previous
#include <cuda_runtime.h>
#include <math.h>

#define H 1024
#define L 512
#define V 50257

// ---------------- scratch layout (floats) ----------------
#define OFF_ALOG   0        // attn logits (512)
#define OFF_ATT    512      // attn_applied accumulator (1024)
#define OFF_X      1536     // GRU input x (1024)
#define OFF_GI     2560     // gi (3072)
#define OFF_GH     5632     // gh (3072)
#define OFF_HNEW   8704     // h_new (1024)
#define OFF_LOGITS 9728     // vocab logits (50257)
#define OFF_PART   59985    // 240 partial exp-sums
#define OFF_LSE    60225
#define SCRATCH_FLOATS 60240

__device__ float g_scratch[SCRATCH_FLOATS];
__device__ int   g_maxbits;   // ordered-int running max of vocab logits
__device__ int   g_count_ls;  // arrival counter: log-softmax
__device__ int   g_flag_ls;   // lse-ready flag

__device__ __forceinline__ int f2ord(float f) {
    int i = __float_as_int(f);
    return (i >= 0) ? i : (i ^ 0x7FFFFFFF);
}
__device__ __forceinline__ float ord2f(int o) {
    return __int_as_float((o >= 0) ? o : (o ^ 0x7FFFFFFF));
}

// dot of 8 front-batched float4 (1024 floats) against smem slice
__device__ __forceinline__ float dot8(const float4* __restrict__ wr,
                                      const float4* __restrict__ v4,
                                      int lane) {
    float4 w0 = __ldcs(wr + lane);
    float4 w1 = __ldcs(wr + lane + 32);
    float4 w2 = __ldcs(wr + lane + 64);
    float4 w3 = __ldcs(wr + lane + 96);
    float4 w4 = __ldcs(wr + lane + 128);
    float4 w5 = __ldcs(wr + lane + 160);
    float4 w6 = __ldcs(wr + lane + 192);
    float4 w7 = __ldcs(wr + lane + 224);
    float4 x0 = v4[lane],       x1 = v4[lane + 32];
    float4 x2 = v4[lane + 64],  x3 = v4[lane + 96];
    float4 x4 = v4[lane + 128], x5 = v4[lane + 160];
    float4 x6 = v4[lane + 192], x7 = v4[lane + 224];
    float a = 0.f;
    a += w0.x*x0.x + w0.y*x0.y + w0.z*x0.z + w0.w*x0.w;
    a += w1.x*x1.x + w1.y*x1.y + w1.z*x1.z + w1.w*x1.w;
    a += w2.x*x2.x + w2.y*x2.y + w2.z*x2.z + w2.w*x2.w;
    a += w3.x*x3.x + w3.y*x3.y + w3.z*x3.z + w3.w*x3.w;
    a += w4.x*x4.x + w4.y*x4.y + w4.z*x4.z + w4.w*x4.w;
    a += w5.x*x5.x + w5.y*x5.y + w5.z*x5.z + w5.w*x5.w;
    a += w6.x*x6.x + w6.y*x6.y + w6.z*x6.z + w6.w*x6.w;
    a += w7.x*x7.x + w7.y*x7.y + w7.z*x7.z + w7.w*x7.w;
    return a;
}

// dot of 4 front-batched float4 (512 floats = half of a 1024-col row)
__device__ __forceinline__ float dot4(const float4* __restrict__ wr,
                                      const float4* __restrict__ v4,
                                      int lane) {
    float4 w0 = __ldcs(wr + lane);
    float4 w1 = __ldcs(wr + lane + 32);
    float4 w2 = __ldcs(wr + lane + 64);
    float4 w3 = __ldcs(wr + lane + 96);
    float4 x0 = v4[lane],      x1 = v4[lane + 32];
    float4 x2 = v4[lane + 64], x3 = v4[lane + 96];
    float a = 0.f;
    a += w0.x*x0.x + w0.y*x0.y + w0.z*x0.z + w0.w*x0.w;
    a += w1.x*x1.x + w1.y*x1.y + w1.z*x1.z + w1.w*x1.w;
    a += w2.x*x2.x + w2.y*x2.y + w2.z*x2.z + w2.w*x2.w;
    a += w3.x*x3.x + w3.y*x3.y + w3.z*x3.z + w3.w*x3.w;
    return a;
}

__device__ __forceinline__ float warp_sum(float a) {
    #pragma unroll
    for (int o = 16; o; o >>= 1) a += __shfl_xor_sync(0xFFFFFFFFu, a, o);
    return a;
}

// ---------------- N1: attn logits (blocks 0-127) + gh GEMV (blocks 128-895) ----------------
// 256 threads: 8 warps = 4 rows x 2 half-row tasks per block.
__global__ void __launch_bounds__(256)
k_attn_gh(const float* __restrict__ attn_W, const float* __restrict__ attn_b,
          const float* __restrict__ W_hh, const float* __restrict__ b_hh,
          const int* __restrict__ idx, const float* __restrict__ hidden,
          const float* __restrict__ emb) {
    __shared__ float sv[2 * H];
    __shared__ float spart[8];
    int t = threadIdx.x, bid = blockIdx.x;
    int warp = t >> 5, lane = t & 31;

    if (bid < 128) {
        int row_e = idx[0];
        #pragma unroll
        for (int i = t; i < 512; i += 256) {
            ((float4*)sv)[i] = (i < 256)
                ? ((const float4*)(emb + (size_t)row_e * H))[i]
                : ((const float4*)hidden)[i - 256];
        }
    } else {
        if (t < 256) {
            #pragma unroll
            for (int i = t; i < 256; i += 256)
                ((float4*)sv)[i] = ((const float4*)hidden)[i];
        }
    }
    if (bid == 0) {
        #pragma unroll
        for (int i = t; i < H; i += 256) g_scratch[OFF_ATT + i] = 0.f;
        if (t == 0) { g_maxbits = 0x80000000; g_count_ls = 0; g_flag_ls = 0; }
    }
    __syncthreads();

    if (bid < 128) {
        // attn: rows bid*4 .. bid*4+3, each row = 2048 cols -> 2 dot8 halves
        int row  = bid * 4 + (warp >> 1);
        int half = warp & 1;
        const float4* wr = (const float4*)(attn_W + (size_t)row * 2 * H + half * H);
        float acc = warp_sum(dot8(wr, (const float4*)(sv + half * H), lane));
        if (lane == 0) spart[warp] = acc;
        __syncthreads();
        if (t < 4) {
            int r = bid * 4 + t;
            g_scratch[OFF_ALOG + r] = spart[2 * t] + spart[2 * t + 1] + attn_b[r];
        }
    } else {
        // gh: rows (bid-128)*4 .., each row = 1024 cols -> 2 dot4 halves
        int row  = (bid - 128) * 4 + (warp >> 1);
        int half = warp & 1;
        const float4* wr = (const float4*)(W_hh + (size_t)row * H + half * 512);
        float acc = warp_sum(dot4(wr, (const float4*)(sv + half * 512), lane));
        if (lane == 0) spart[warp] = acc;
        __syncthreads();
        if (t < 4) {
            int r = (bid - 128) * 4 + t;
            g_scratch[OFF_GH + r] = spart[2 * t] + spart[2 * t + 1] + b_hh[r];
        }
    }
}

// ---------------- N2: per-block softmax(512) + attn_applied partials ----------------
__global__ void __launch_bounds__(256)
k_apply(const float* __restrict__ enc, float* __restrict__ out_full) {
    __shared__ float aw[512];
    __shared__ float sred[256];
    int t = threadIdx.x;
    float v0 = g_scratch[OFF_ALOG + t];
    float v1 = g_scratch[OFF_ALOG + 256 + t];
    sred[t] = fmaxf(v0, v1);
    __syncthreads();
    #pragma unroll
    for (int s = 128; s > 0; s >>= 1) {
        if (t < s) sred[t] = fmaxf(sred[t], sred[t + s]);
        __syncthreads();
    }
    float mx = sred[0];
    __syncthreads();
    float e0 = expf(v0 - mx), e1 = expf(v1 - mx);
    sred[t] = e0 + e1;
    __syncthreads();
    #pragma unroll
    for (int s = 128; s > 0; s >>= 1) {
        if (t < s) sred[t] += sred[t + s];
        __syncthreads();
    }
    float inv = 1.f / sred[0];
    aw[t] = e0 * inv; aw[256 + t] = e1 * inv;
    __syncthreads();
    if (blockIdx.x == 0 && blockIdx.y == 0) {
        out_full[V + H + t]       = aw[t];
        out_full[V + H + 256 + t] = aw[256 + t];
    }
    int col  = blockIdx.x * 256 + t;
    int base = blockIdx.y * 32;
    float s = 0.f;
    #pragma unroll
    for (int l = 0; l < 32; l++)
        s += aw[base + l] * __ldcs(enc + (size_t)(base + l) * H + col);
    atomicAdd(&g_scratch[OFF_ATT + col], s);
}

// ---------------- N3: x = relu(cat(emb[idx], attn_applied) @ comb_W.T + b) ----------------
// 256 blocks x 256 thr: 4 rows x 2 half-row (dot8) tasks.
__global__ void __launch_bounds__(256)
k_comb(const float* __restrict__ comb_W, const float* __restrict__ comb_b,
       const int* __restrict__ idx, const float* __restrict__ emb) {
    __shared__ float sv[2 * H];
    __shared__ float spart[8];
    int t = threadIdx.x;
    int warp = t >> 5, lane = t & 31;
    int row_e = idx[0];
    #pragma unroll
    for (int i = t; i < 512; i += 256) {
        ((float4*)sv)[i] = (i < 256)
            ? ((const float4*)(emb + (size_t)row_e * H))[i]
            : ((const float4*)(g_scratch + OFF_ATT))[i - 256];
    }
    __syncthreads();
    int row  = blockIdx.x * 4 + (warp >> 1);
    int half = warp & 1;
    const float4* wr = (const float4*)(comb_W + (size_t)row * 2 * H + half * H);
    float acc = warp_sum(dot8(wr, (const float4*)(sv + half * H), lane));
    if (lane == 0) spart[warp] = acc;
    __syncthreads();
    if (t < 4) {
        int r = blockIdx.x * 4 + t;
        g_scratch[OFF_X + r] = fmaxf(spart[2 * t] + spart[2 * t + 1] + comb_b[r], 0.f);
    }
}

// ---------------- N4: gi = x @ W_ih.T + b_ih ----------------
// 768 blocks x 256 thr: 4 rows x 2 half-row (dot4) tasks -> 41.5 warps/SM.
__global__ void __launch_bounds__(256)
k_gi(const float* __restrict__ W_ih, const float* __restrict__ b_ih) {
    __shared__ float sx[H];
    __shared__ float spart[8];
    int t = threadIdx.x;
    if (t < 256) ((float4*)sx)[t] = ((const float4*)(g_scratch + OFF_X))[t];
    __syncthreads();
    int warp = t >> 5, lane = t & 31;
    int row  = blockIdx.x * 4 + (warp >> 1);
    int half = warp & 1;
    const float4* wr = (const float4*)(W_ih + (size_t)row * H + half * 512);
    float acc = warp_sum(dot4(wr, (const float4*)(sx + half * 512), lane));
    if (lane == 0) spart[warp] = acc;
    __syncthreads();
    if (t < 4) {
        int r = blockIdx.x * 4 + t;
        g_scratch[OFF_GI + r] = spart[2 * t] + spart[2 * t + 1] + b_ih[r];
    }
}

// ---------------- N5: GRU gates -> h_new (tiny, once) ----------------
__global__ void k_gates(const float* __restrict__ hidden, float* __restrict__ out_full) {
    int j = blockIdx.x * 512 + threadIdx.x;   // 0..1023
    float gir = g_scratch[OFF_GI + j],       ghr = g_scratch[OFF_GH + j];
    float giz = g_scratch[OFF_GI + H + j],   ghz = g_scratch[OFF_GH + H + j];
    float gin = g_scratch[OFF_GI + 2*H + j], ghn = g_scratch[OFF_GH + 2*H + j];
    float r = 1.f / (1.f + expf(-(gir + ghr)));
    float z = 1.f / (1.f + expf(-(giz + ghz)));
    float n = tanhf(gin + r * ghn);
    float hn = (1.f - z) * n + z * hidden[j];
    g_scratch[OFF_HNEW + j] = hn;
    out_full[V + j] = hn;                     // second output
}

// ---------------- N6: vocab logits, loop-persistent (all blocks resident) ----------------
#define VB 1184                                // blocks; 4 warps each -> 4736 warp-lanes
__global__ void __launch_bounds__(128)
k_vocab(const float* __restrict__ out_W, const float* __restrict__ out_b) {
    __shared__ float hv[H];
    __shared__ float smax[4];
    int t = threadIdx.x;
    ((float4*)hv)[t]       = ((const float4*)(g_scratch + OFF_HNEW))[t];
    ((float4*)hv)[t + 128] = ((const float4*)(g_scratch + OFF_HNEW))[t + 128];
    __syncthreads();
    int warp = t >> 5, lane = t & 31;
    int gw = blockIdx.x * 4 + warp;            // 0..4735
    float m = -INFINITY;
    for (int row = gw; row < V; row += VB * 4) {
        const float4* wr = (const float4*)(out_W + (size_t)row * H);
        float acc = warp_sum(dot8(wr, (const float4*)hv, lane));
        if (lane == 0) {
            float r = acc + out_b[row];
            g_scratch[OFF_LOGITS + row] = r;
            m = fmaxf(m, r);
        }
    }
    if (lane == 0) smax[warp] = m;
    __syncthreads();
    if (t == 0) {
        float bm = fmaxf(fmaxf(smax[0], smax[1]), fmaxf(smax[2], smax[3]));
        atomicMax(&g_maxbits, f2ord(bm));
    }
}

// ---------------- N7: fused log-softmax (240 blocks, one wave, spin on lse) ----------------
#define NB_SUM 240
__global__ void __launch_bounds__(256)
k_logsoftmax(float* __restrict__ out_full) {
    __shared__ float sm[256];
    int t = threadIdx.x;
    float m = ord2f(g_maxbits);
    float s = 0.f;
    for (int i = blockIdx.x * 256 + t; i < V; i += NB_SUM * 256)
        s += expf(g_scratch[OFF_LOGITS + i] - m);
    sm[t] = s;
    __syncthreads();
    #pragma unroll
    for (int st = 128; st > 0; st >>= 1) {
        if (t < st) sm[t] += sm[t + st];
        __syncthreads();
    }
    if (t == 0) {
        g_scratch[OFF_PART + blockIdx.x] = sm[0];
        __threadfence();
        int old = atomicAdd(&g_count_ls, 1);
        if (old == NB_SUM - 1) {
            float tot = 0.f;
            #pragma unroll 8
            for (int p = 0; p < NB_SUM; p++) tot += g_scratch[OFF_PART + p];
            g_scratch[OFF_LSE] = m + logf(tot);
            __threadfence();
            atomicExch(&g_flag_ls, 1);
        }
        while (atomicAdd(&g_flag_ls, 0) == 0) { }
        __threadfence();
    }
    __syncthreads();
    float lse = g_scratch[OFF_LSE];
    for (int i = blockIdx.x * 256 + t; i < V; i += NB_SUM * 256)
        out_full[i] = g_scratch[OFF_LOGITS + i] - lse;
}

// ---------------- launch: 7 graph nodes ----------------
extern "C" void kernel_launch(void* const* d_in, const int* in_sizes, int n_in,
                              void* d_out, int out_size) {
    const int*   input_idx = (const int*)  d_in[0];
    const float* hidden    = (const float*)d_in[1];
    const float* enc       = (const float*)d_in[2];
    const float* emb       = (const float*)d_in[3];
    const float* attn_W    = (const float*)d_in[4];
    const float* attn_b    = (const float*)d_in[5];
    const float* comb_W    = (const float*)d_in[6];
    const float* comb_b    = (const float*)d_in[7];
    const float* W_ih      = (const float*)d_in[8];
    const float* W_hh      = (const float*)d_in[9];
    const float* b_ih      = (const float*)d_in[10];
    const float* b_hh      = (const float*)d_in[11];
    const float* out_W     = (const float*)d_in[12];
    const float* out_b     = (const float*)d_in[13];
    float* out = (float*)d_out;

    k_attn_gh   <<<896, 256>>>(attn_W, attn_b, W_hh, b_hh, input_idx, hidden, emb);
    k_apply     <<<dim3(4, 16), 256>>>(enc, out);
    k_comb      <<<256, 256>>>(comb_W, comb_b, input_idx, emb);
    k_gi        <<<768, 256>>>(W_ih, b_ih);
    k_gates     <<<2, 512>>>(hidden, out);
    k_vocab     <<<VB, 128>>>(out_W, out_b);
    k_logsoftmax<<<NB_SUM, 256>>>(out);
}